// round 12
// baseline (speedup 1.0000x reference)
#include <cuda_runtime.h>
#include <cuda_fp16.h>
#include <cstdint>

#define IN_CH   128
#define OUT_CH  128
#define NDEG    81
#define NCPT    17
#define P_TOT   6561
#define XB_STRIDE (IN_CH * P_TOT)

#define WROW 136                 // padded k-row length in fp16 (272 bytes)
#define WBLK (128 * WROW)        // per-degree elems (34816 B)
#define NT   7                   // tiles per CTA -> 276 working CTAs = 1 wave

__device__ __align__(16) __half wA[NDEG * WBLK];
__device__ __align__(16) float  wT[NCPT * IN_CH * OUT_CH];   // [s][k*128+o]

__device__ __forceinline__ unsigned smem_u32(const void* p) {
    unsigned a;
    asm("{ .reg .u64 t; cvta.to.shared.u64 t, %1; cvt.u32.u64 %0, t; }"
        : "=r"(a) : "l"(p));
    return a;
}

#define LDSM4(R, ADDR)                                                        \
    asm volatile("ldmatrix.sync.aligned.m8n8.x4.shared.b16 "                  \
                 "{%0,%1,%2,%3}, [%4];"                                       \
                 : "=r"((R)[0]), "=r"((R)[1]), "=r"((R)[2]), "=r"((R)[3])     \
                 : "r"(ADDR))

#define MMA16816(D, A, B0, B1)                                                \
    asm volatile("mma.sync.aligned.m16n8k16.row.col.f32.f16.f16.f32 "         \
                 "{%0,%1,%2,%3},{%4,%5,%6,%7},{%8,%9},{%0,%1,%2,%3};"         \
                 : "+f"((D)[0]), "+f"((D)[1]), "+f"((D)[2]), "+f"((D)[3])     \
                 : "r"((A)[0]), "r"((A)[1]), "r"((A)[2]), "r"((A)[3]),        \
                   "r"(B0), "r"(B1))

#define CPA16(DST, SRC)                                                       \
    asm volatile("cp.async.cg.shared.global [%0], [%1], 16;"                  \
                 :: "r"(DST), "l"(SRC))

// ---------------------------------------------------------------------------
// Kernel 0: transpose w[k][o][17] -> wT[s][k*128+o].
// Each thread owns one (k,o): reads 68 contiguous bytes, writes 17
// lane-coalesced stores.
// ---------------------------------------------------------------------------
__global__ __launch_bounds__(256) void shconv_transpose(const float* __restrict__ w)
{
    const int t = blockIdx.x * 256 + threadIdx.x;     // k*128+o
    const float* src = w + t * NCPT;
#pragma unroll
    for (int s = 0; s < NCPT; s++)
        wT[s * (IN_CH * OUT_CH) + t] = src[s];
}

// ---------------------------------------------------------------------------
// Kernel 1: pack. CTA = (degree l, 32-k chunk). Reads 2 contiguous anchor
// slabs (coalesced), interpolates into smem tile (pitch 129, conflict-free),
// transposes to [o][k] fp16 with 32B-contiguous stores.
// ---------------------------------------------------------------------------
__global__ __launch_bounds__(256) void shconv_pack()
{
    __shared__ float tile[32][129];
    const int l  = blockIdx.x;
    const int k0 = blockIdx.y * 32;

    int s; float t;
    if (l < 75) { s = l / 5; t = (float)(l - s * 5) * 0.2f; }
    else        { s = 15;    t = (float)(l - 75) * 0.2f; }

    const float* a0 = wT + s * (IN_CH * OUT_CH) + k0 * OUT_CH;
    const float* a1 = a0 + (IN_CH * OUT_CH);

    for (int e = threadIdx.x; e < 32 * 128; e += 256) {
        const int kk = e >> 7, o = e & 127;
        tile[kk][o] = (1.0f - t) * a0[e] + t * a1[e];
    }
    __syncthreads();

    // thread -> (o = tid>>1, kh = tid&1): 16 consecutive k as 2 uint4
    const int o  = threadIdx.x >> 1;
    const int kh = threadIdx.x & 1;
    unsigned pk[8];
#pragma unroll
    for (int j = 0; j < 8; j++) {
        const __half h0 = __float2half_rn(tile[kh * 16 + 2 * j][o]);
        const __half h1 = __float2half_rn(tile[kh * 16 + 2 * j + 1][o]);
        pk[j] = ((unsigned)__half_as_ushort(h1) << 16) | __half_as_ushort(h0);
    }
    char* dst = (char*)wA + l * (WBLK * 2) + o * 272 + (k0 + kh * 16) * 2;
    uint4 v0 = { pk[0], pk[1], pk[2], pk[3] };
    uint4 v1 = { pk[4], pk[5], pk[6], pk[7] };
    *(uint4*)(dst)      = v0;
    *(uint4*)(dst + 16) = v1;
}

// ---------------------------------------------------------------------------
// Kernel 2: 256-thread fp16 HMMA GEMM, W fragments hoisted, NT=7 (1 wave).
// All coloff generations precomputed in prologue. Loop identical to round 11.
// smem: Wstage/EPI 36864 | B 17408 | coloff[7][64]
// ---------------------------------------------------------------------------
#define SM_EPI  0
#define SM_B    36864
#define SM_COL  54272
#define DSMEM   56064

__global__ __launch_bounds__(256, 2) void shconv_mma(const float* __restrict__ x,
                                                     float* __restrict__ out)
{
    const int l      = 80 - blockIdx.y;          // LPT: big degrees first
    const int ntiles = (l >> 1) + 1;
    const int t0     = blockIdx.x * NT;
    int nt = ntiles - t0;
    if (nt <= 0) return;
    if (nt > NT) nt = NT;

    extern __shared__ __align__(16) char sm[];
    int*   coloff = (int*)(sm + SM_COL);         // [7][64]
    float* ep     = (float*)(sm + SM_EPI);       // [128][72] after hoist
    const unsigned sb = smem_u32(sm);

    const int tid  = threadIdx.x;
    const int lane = tid & 31;
    const int wid  = tid >> 5;
    const int span  = 2 * l + 1;
    const int ncols = 16 * span;

    // --- W: cp.async into the (soon to be EPI) staging region ---
    {
        const char* gw = (const char*)(wA + l * WBLK);
#pragma unroll
        for (int j = 0; j < 9; j++) {
            const int e = tid + 256 * j;
            if (e < 2176)
                CPA16(sb + SM_EPI + e * 16, gw + e * 16);
        }
        asm volatile("cp.async.commit_group;" ::: "memory");
    }

    // --- ALL coloff generations upfront (no per-tile writes, no races) ---
    for (int e = tid; e < nt * 64; e += 256) {
        const int c  = t0 * 64 + e;
        const int cc = c < ncols ? c : ncols - 1;
        const int b  = cc / span;
        coloff[e] = b * XB_STRIDE + l * l + (cc - b * span);
    }
    asm volatile("cp.async.wait_group 0;" ::: "memory");
    __syncthreads();

    // --- HOIST: ldmatrix all 8 k-step A fragments once (W tile-invariant) ---
    const int m_base = wid * 16;
    unsigned aF[8][4];
    {
        const unsigned aoff = (unsigned)(m_base + (lane & 15)) * 272u
                            + (unsigned)(lane >> 4) * 16u;
        const unsigned aW = sb + SM_EPI + aoff;
#pragma unroll
        for (int ks = 0; ks < 8; ks++)
            LDSM4(aF[ks], aW + (unsigned)ks * 32u);
    }

    // --- X ownership: col xc, k in [kb,kb+32); eager fp16 pack (16 words) ---
    const int xc = tid & 63;
    const int kb = (tid >> 6) * 32;
    unsigned xh[16];
    {
        const float* xp = x + coloff[xc];
#pragma unroll
        for (int m = 0; m < 16; m++) {
            const __half h0 = __float2half_rn(xp[(kb + 2 * m) * P_TOT]);
            const __half h1 = __float2half_rn(xp[(kb + 2 * m + 1) * P_TOT]);
            xh[m] = ((unsigned)__half_as_ushort(h1) << 16) | __half_as_ushort(h0);
        }
    }

    // --- B fragment addresses: 4 n-groups of 16 cols each ---
    const unsigned boff = (unsigned)(((lane & 7) | ((lane >> 4) << 3))) * 272u
                        + (unsigned)((lane >> 3) & 1) * 16u;
    const unsigned bB = sb + SM_B + boff;

    char* bp = sm + SM_B;
    const int ec = tid & 63;                     // epilogue column
    const int ob = tid >> 6;                     // epilogue row base (0..3)

    for (int tt = 0; tt < nt; tt++) {
        // --- STS xh(tt) -> B (4x16B contiguous) ---
        {
            char* dst = bp + xc * 272 + kb * 2;
            uint4 v0 = { xh[0],  xh[1],  xh[2],  xh[3]  };
            uint4 v1 = { xh[4],  xh[5],  xh[6],  xh[7]  };
            uint4 v2 = { xh[8],  xh[9],  xh[10], xh[11] };
            uint4 v3 = { xh[12], xh[13], xh[14], xh[15] };
            *(uint4*)(dst)      = v0;
            *(uint4*)(dst + 16) = v1;
            *(uint4*)(dst + 32) = v2;
            *(uint4*)(dst + 48) = v3;
        }
        __syncthreads();                          // sync1: B(tt) visible

        // --- LDG + convert X(tt+1) (lands during MMA below) ---
        if (tt + 1 < nt) {
            const float* xp = x + coloff[(tt + 1) * 64 + xc];
#pragma unroll
            for (int m = 0; m < 16; m++) {
                const __half h0 = __float2half_rn(xp[(kb + 2 * m) * P_TOT]);
                const __half h1 = __float2half_rn(xp[(kb + 2 * m + 1) * P_TOT]);
                xh[m] = ((unsigned)__half_as_ushort(h1) << 16) | __half_as_ushort(h0);
            }
        }

        // --- MMA: 8 k-steps, B-LDSM only, 8 independent acc chains ---
        float acc[8][4];
#pragma unroll
        for (int nq = 0; nq < 8; nq++)
#pragma unroll
            for (int j = 0; j < 4; j++) acc[nq][j] = 0.0f;

#pragma unroll
        for (int ks = 0; ks < 8; ks++) {
            const unsigned ko = (unsigned)ks * 32u;
            unsigned bf[4][4];
#pragma unroll
            for (int g = 0; g < 4; g++)
                LDSM4(bf[g], bB + (unsigned)g * (16u * 272u) + ko);
#pragma unroll
            for (int g = 0; g < 4; g++) {
                MMA16816(acc[2 * g],     aF[ks], bf[g][0], bf[g][1]);
                MMA16816(acc[2 * g + 1], aF[ks], bf[g][2], bf[g][3]);
            }
        }

        // --- STS acc -> EPI scratch (pitch 72, conflict-free STS.64) ---
        {
            const int r = m_base + (lane >> 2);
#pragma unroll
            for (int nq = 0; nq < 8; nq++) {
                const int cc = nq * 8 + (lane & 3) * 2;
                float2 lo = { acc[nq][0], acc[nq][1] };
                float2 hi = { acc[nq][2], acc[nq][3] };
                *(float2*)&ep[r * 72 + cc]       = lo;
                *(float2*)&ep[(r + 8) * 72 + cc] = hi;
            }
        }
        __syncthreads();                          // sync2: EPI complete

        // --- coalesced epilogue: lanes sweep consecutive c -> 128B lines ---
        if ((t0 + tt) * 64 + ec < ncols) {
            float* op = out + coloff[tt * 64 + ec] + ob * P_TOT;
            const float* rp = ep + ob * 72 + ec;
#pragma unroll
            for (int j = 0; j < 32; j++)
                op[j * 4 * P_TOT] = rp[j * 4 * 72];
        }
        // no third barrier: B rewritten only after all warps passed sync2;
        // EPI rewritten only after next sync1; coloff never rewritten.
    }
}

extern "C" void kernel_launch(void* const* d_in, const int* in_sizes, int n_in,
                              void* d_out, int out_size)
{
    const float* x = (const float*)d_in[0];      // [16,128,6561]
    const float* w = (const float*)d_in[1];      // [128,128,17,1]
    float* out = (float*)d_out;                  // [16,128,6561]

    cudaFuncSetAttribute(shconv_mma,
                         cudaFuncAttributeMaxDynamicSharedMemorySize, DSMEM);

    shconv_transpose<<<64, 256>>>(w);            // w -> wT
    dim3 pg(NDEG, 4);
    shconv_pack<<<pg, 256>>>();                  // wT -> wA (fp16 padded)

    dim3 grid(6, NDEG);                          // 7-tile chunks x degrees
    shconv_mma<<<grid, 256, DSMEM>>>(x, out);
}

// round 13
// speedup vs baseline: 1.0220x; 1.0220x over previous
#include <cuda_runtime.h>
#include <cuda_fp16.h>
#include <cstdint>

#define IN_CH   128
#define OUT_CH  128
#define NDEG    81
#define NCPT    17
#define P_TOT   6561
#define XB_STRIDE (IN_CH * P_TOT)

#define WROW 136                 // padded k-row length in fp16 (272 bytes)
#define WBLK (128 * WROW)        // per-degree elems (34816 B)
#define NT   3                   // tiles per CTA (round-11 proven)

__device__ __align__(16) __half wA[NDEG * WBLK];

__device__ __forceinline__ unsigned smem_u32(const void* p) {
    unsigned a;
    asm("{ .reg .u64 t; cvta.to.shared.u64 t, %1; cvt.u32.u64 %0, t; }"
        : "=r"(a) : "l"(p));
    return a;
}

#define LDSM4(R, ADDR)                                                        \
    asm volatile("ldmatrix.sync.aligned.m8n8.x4.shared.b16 "                  \
                 "{%0,%1,%2,%3}, [%4];"                                       \
                 : "=r"((R)[0]), "=r"((R)[1]), "=r"((R)[2]), "=r"((R)[3])     \
                 : "r"(ADDR))

#define MMA16816(D, A, B0, B1)                                                \
    asm volatile("mma.sync.aligned.m16n8k16.row.col.f32.f16.f16.f32 "         \
                 "{%0,%1,%2,%3},{%4,%5,%6,%7},{%8,%9},{%0,%1,%2,%3};"         \
                 : "+f"((D)[0]), "+f"((D)[1]), "+f"((D)[2]), "+f"((D)[3])     \
                 : "r"((A)[0]), "r"((A)[1]), "r"((A)[2]), "r"((A)[3]),        \
                   "r"(B0), "r"(B1))

#define CPA16(DST, SRC)                                                       \
    asm volatile("cp.async.cg.shared.global [%0], [%1], 16;"                  \
                 :: "r"(DST), "l"(SRC))
#define CPA4(DST, SRC)                                                        \
    asm volatile("cp.async.ca.shared.global [%0], [%1], 4;"                   \
                 :: "r"(DST), "l"(SRC))

// ---------------------------------------------------------------------------
// Kernel 1: interp + pack (round-11 version — single kernel, ~5us).
// ---------------------------------------------------------------------------
__global__ __launch_bounds__(256) void shconv_interp_pack(const float* __restrict__ w)
{
    __shared__ float anch[32][NCPT];
    const int o  = blockIdx.x >> 2;
    const int k0 = (blockIdx.x & 3) * 32;

    for (int e = threadIdx.x; e < 32 * NCPT; e += 256) {
        const int kk = e / NCPT, s = e % NCPT;
        anch[kk][s] = w[((k0 + kk) * OUT_CH + o) * NCPT + s];
    }
    __syncthreads();

    for (int e = threadIdx.x; e < NDEG * 32; e += 256) {
        const int l  = e >> 5;
        const int kk = e & 31;
        int s; float t;
        if (l < 75) { s = l / 5; t = (float)(l - s * 5) * 0.2f; }
        else        { s = 15;    t = (float)(l - 75) * 0.2f; }
        const float v = (1.0f - t) * anch[kk][s] + t * anch[kk][s + 1];
        wA[l * WBLK + o * WROW + k0 + kk] = __float2half_rn(v);
    }
}

// ---------------------------------------------------------------------------
// Kernel 2: fp16 HMMA GEMM; X staged via 4B cp.async (no per-tile LDG stall).
// 8 warps, warp-tile 16m x 64n, A fragments hoisted once per CTA.
// Per tile: wait(X) -> LDS/CVT/STS-B (thread-private cells) -> cp.async X(t+1)
//           -> sync1 -> MMA -> STS-EPI -> sync2 -> coalesced epilogue.
// smem: Wstage/EPI 36864 | B 17408 | XF fp32 [128k][64c] 32768 | coloff[3][64]
// ---------------------------------------------------------------------------
#define SM_EPI  0
#define SM_B    36864
#define SM_XF   54272
#define SM_COL  87040
#define DSMEM   87808

__global__ __launch_bounds__(256, 2) void shconv_mma(const float* __restrict__ x,
                                                     float* __restrict__ out)
{
    const int l      = 80 - blockIdx.y;          // LPT: big degrees first
    const int ntiles = (l >> 1) + 1;
    const int t0     = blockIdx.x * NT;
    int nt = ntiles - t0;
    if (nt <= 0) return;
    if (nt > NT) nt = NT;

    extern __shared__ __align__(16) char sm[];
    int*   coloff = (int*)(sm + SM_COL);         // [3][64]
    float* ep     = (float*)(sm + SM_EPI);       // [128][72] after hoist
    const unsigned sb = smem_u32(sm);

    const int tid  = threadIdx.x;
    const int lane = tid & 31;
    const int wid  = tid >> 5;
    const int span  = 2 * l + 1;
    const int ncols = 16 * span;

    // --- W: cp.async into the (soon-to-be EPI) staging region ---
    {
        const char* gw = (const char*)(wA + l * WBLK);
#pragma unroll
        for (int j = 0; j < 9; j++) {
            const int e = tid + 256 * j;
            if (e < 2176)
                CPA16(sb + SM_EPI + e * 16, gw + e * 16);
        }
    }

    // --- ALL coloff generations upfront ---
    for (int e = tid; e < nt * 64; e += 256) {
        const int c  = t0 * 64 + e;
        const int cc = c < ncols ? c : ncols - 1;
        const int b  = cc / span;
        coloff[e] = b * XB_STRIDE + l * l + (cc - b * span);
    }
    __syncthreads();                              // coloff visible

    // --- X(t0): 4B cp.async into XF[k][c] (thread owns col xc, 32 k) ---
    const int xc = tid & 63;
    const int kb = (tid >> 6) * 32;
    const unsigned xfbase = sb + SM_XF + (unsigned)xc * 4u;
    {
        const float* xp = x + coloff[xc];
#pragma unroll
        for (int j = 0; j < 32; j++)
            CPA4(xfbase + (unsigned)(kb + j) * 256u, xp + (kb + j) * P_TOT);
    }
    asm volatile("cp.async.commit_group;" ::: "memory");
    asm volatile("cp.async.wait_group 0;" ::: "memory");
    __syncthreads();                              // W visible for hoist

    // --- HOIST: ldmatrix all 8 k-step A fragments once ---
    const int m_base = wid * 16;
    unsigned aF[8][4];
    {
        const unsigned aoff = (unsigned)(m_base + (lane & 15)) * 272u
                            + (unsigned)(lane >> 4) * 16u;
        const unsigned aW = sb + SM_EPI + aoff;
#pragma unroll
        for (int ks = 0; ks < 8; ks++)
            LDSM4(aF[ks], aW + (unsigned)ks * 32u);
    }

    // --- B fragment addresses: 4 n-groups of 16 cols each ---
    const unsigned boff = (unsigned)(((lane & 7) | ((lane >> 4) << 3))) * 272u
                        + (unsigned)((lane >> 3) & 1) * 16u;
    const unsigned bB = sb + SM_B + boff;

    char* bp = sm + SM_B;
    const float* xfp = (const float*)(sm + SM_XF) + xc;   // [k][64] row pitch 64
    const int ec = tid & 63;                     // epilogue column
    const int ob = tid >> 6;                     // epilogue row base (0..3)

    for (int tt = 0; tt < nt; tt++) {
        // X(tt) already landed (wait in prologue / previous iteration).
        // --- LDS own fp32 cells -> CVT fp16 -> STS-B (all thread-private) ---
        {
            unsigned xh[16];
#pragma unroll
            for (int m = 0; m < 16; m++) {
                const float v0 = xfp[(kb + 2 * m) * 64];
                const float v1 = xfp[(kb + 2 * m + 1) * 64];
                const __half h0 = __float2half_rn(v0);
                const __half h1 = __float2half_rn(v1);
                xh[m] = ((unsigned)__half_as_ushort(h1) << 16) | __half_as_ushort(h0);
            }
            char* dst = bp + xc * 272 + kb * 2;
            uint4 v0 = { xh[0],  xh[1],  xh[2],  xh[3]  };
            uint4 v1 = { xh[4],  xh[5],  xh[6],  xh[7]  };
            uint4 v2 = { xh[8],  xh[9],  xh[10], xh[11] };
            uint4 v3 = { xh[12], xh[13], xh[14], xh[15] };
            *(uint4*)(dst)      = v0;
            *(uint4*)(dst + 16) = v1;
            *(uint4*)(dst + 32) = v2;
            *(uint4*)(dst + 48) = v3;
        }
        // --- fire cp.async X(tt+1) into same (own) XF cells ---
        if (tt + 1 < nt) {
            const float* xp = x + coloff[(tt + 1) * 64 + xc];
#pragma unroll
            for (int j = 0; j < 32; j++)
                CPA4(xfbase + (unsigned)(kb + j) * 256u, xp + (kb + j) * P_TOT);
            asm volatile("cp.async.commit_group;" ::: "memory");
        }
        __syncthreads();                          // sync1: B(tt) visible

        // --- MMA: 8 k-steps, B-LDSM only, 8 independent acc chains ---
        float acc[8][4];
#pragma unroll
        for (int nq = 0; nq < 8; nq++)
#pragma unroll
            for (int j = 0; j < 4; j++) acc[nq][j] = 0.0f;

#pragma unroll
        for (int ks = 0; ks < 8; ks++) {
            const unsigned ko = (unsigned)ks * 32u;
            unsigned bf[4][4];
#pragma unroll
            for (int g = 0; g < 4; g++)
                LDSM4(bf[g], bB + (unsigned)g * (16u * 272u) + ko);
#pragma unroll
            for (int g = 0; g < 4; g++) {
                MMA16816(acc[2 * g],     aF[ks], bf[g][0], bf[g][1]);
                MMA16816(acc[2 * g + 1], aF[ks], bf[g][2], bf[g][3]);
            }
        }

        // --- STS acc -> EPI scratch (pitch 72, conflict-free STS.64) ---
        {
            const int r = m_base + (lane >> 2);
#pragma unroll
            for (int nq = 0; nq < 8; nq++) {
                const int cc = nq * 8 + (lane & 3) * 2;
                float2 lo = { acc[nq][0], acc[nq][1] };
                float2 hi = { acc[nq][2], acc[nq][3] };
                *(float2*)&ep[r * 72 + cc]       = lo;
                *(float2*)&ep[(r + 8) * 72 + cc] = hi;
            }
        }
        __syncthreads();                          // sync2: EPI complete

        // --- coalesced epilogue: lanes sweep consecutive c -> 128B lines ---
        if ((t0 + tt) * 64 + ec < ncols) {
            float* op = out + coloff[tt * 64 + ec] + ob * P_TOT;
            const float* rp = ep + ob * 72 + ec;
#pragma unroll
            for (int j = 0; j < 32; j++)
                op[j * 4 * P_TOT] = rp[j * 4 * 72];
        }
        // --- ensure X(tt+1) landed before its tile-top LDS ---
        if (tt + 1 < nt)
            asm volatile("cp.async.wait_group 0;" ::: "memory");
        // no third barrier: B rewritten only after all warps passed sync2;
        // EPI rewritten only after next sync1; XF cells are thread-private;
        // coloff never rewritten.
    }
}

extern "C" void kernel_launch(void* const* d_in, const int* in_sizes, int n_in,
                              void* d_out, int out_size)
{
    const float* x = (const float*)d_in[0];      // [16,128,6561]
    const float* w = (const float*)d_in[1];      // [128,128,17,1]
    float* out = (float*)d_out;                  // [16,128,6561]

    cudaFuncSetAttribute(shconv_mma,
                         cudaFuncAttributeMaxDynamicSharedMemorySize, DSMEM);

    shconv_interp_pack<<<512, 256>>>(w);

    dim3 grid(14, NDEG);                         // 3-tile chunks x degrees
    shconv_mma<<<grid, 256, DSMEM>>>(x, out);
}

// round 14
// speedup vs baseline: 1.2611x; 1.2339x over previous
#include <cuda_runtime.h>
#include <cuda_fp16.h>
#include <cstdint>

#define IN_CH   128
#define OUT_CH  128
#define NDEG    81
#define NCPT    17
#define P_TOT   6561
#define XB_STRIDE (IN_CH * P_TOT)

#define WROW 136                 // padded k-row length in fp16 (272 bytes)
#define WBLK (128 * WROW)        // per-degree elems (34816 B)
#define NT   3                   // tiles per CTA (round-11 proven)

__device__ __align__(16) __half wA[NDEG * WBLK];

__device__ __forceinline__ unsigned smem_u32(const void* p) {
    unsigned a;
    asm("{ .reg .u64 t; cvta.to.shared.u64 t, %1; cvt.u32.u64 %0, t; }"
        : "=r"(a) : "l"(p));
    return a;
}

#define LDSM4(R, ADDR)                                                        \
    asm volatile("ldmatrix.sync.aligned.m8n8.x4.shared.b16 "                  \
                 "{%0,%1,%2,%3}, [%4];"                                       \
                 : "=r"((R)[0]), "=r"((R)[1]), "=r"((R)[2]), "=r"((R)[3])     \
                 : "r"(ADDR))

#define MMA16816(D, A, B0, B1)                                                \
    asm volatile("mma.sync.aligned.m16n8k16.row.col.f32.f16.f16.f32 "         \
                 "{%0,%1,%2,%3},{%4,%5,%6,%7},{%8,%9},{%0,%1,%2,%3};"         \
                 : "+f"((D)[0]), "+f"((D)[1]), "+f"((D)[2]), "+f"((D)[3])     \
                 : "r"((A)[0]), "r"((A)[1]), "r"((A)[2]), "r"((A)[3]),        \
                   "r"(B0), "r"(B1))

#define CPA16(DST, SRC)                                                       \
    asm volatile("cp.async.cg.shared.global [%0], [%1], 16;"                  \
                 :: "r"(DST), "l"(SRC))

// ---------------------------------------------------------------------------
// Kernel 1: interp + pack (round-11 proven version).
// ---------------------------------------------------------------------------
__global__ __launch_bounds__(256) void shconv_interp_pack(const float* __restrict__ w)
{
    __shared__ float anch[32][NCPT];
    const int o  = blockIdx.x >> 2;
    const int k0 = (blockIdx.x & 3) * 32;

    for (int e = threadIdx.x; e < 32 * NCPT; e += 256) {
        const int kk = e / NCPT, s = e % NCPT;
        anch[kk][s] = w[((k0 + kk) * OUT_CH + o) * NCPT + s];
    }
    __syncthreads();

    for (int e = threadIdx.x; e < NDEG * 32; e += 256) {
        const int l  = e >> 5;
        const int kk = e & 31;
        int s; float t;
        if (l < 75) { s = l / 5; t = (float)(l - s * 5) * 0.2f; }
        else        { s = 15;    t = (float)(l - 75) * 0.2f; }
        const float v = (1.0f - t) * anch[kk][s] + t * anch[kk][s + 1];
        wA[l * WBLK + o * WROW + k0 + kk] = __float2half_rn(v);
    }
}

// ---------------------------------------------------------------------------
// Kernel 2: fp16 HMMA GEMM, ONE CTA-sync per tile, warp-local epilogue.
// 8 warps, warp-tile 16m x 64n, A fragments hoisted once per CTA.
// Per tile: STS-B[t&1] -> sync -> LDG X(t+1) -> MMA -> warp-private
//           transpose (STS/syncwarp/LDS) -> coalesced STG.
// smem: perwarp-EPI 8x4608 (=Wstage) | B0 17408 | B1 17408 | coloff[3][64]
// ---------------------------------------------------------------------------
#define SM_EPI  0
#define SM_B0   36864
#define SM_B1   54272
#define SM_COL  71680
#define DSMEM   72448

__global__ __launch_bounds__(256, 2) void shconv_mma(const float* __restrict__ x,
                                                     float* __restrict__ out)
{
    const int l      = 80 - blockIdx.y;          // LPT: big degrees first
    const int ntiles = (l >> 1) + 1;
    const int t0     = blockIdx.x * NT;
    int nt = ntiles - t0;
    if (nt <= 0) return;
    if (nt > NT) nt = NT;

    extern __shared__ __align__(16) char sm[];
    int* coloff = (int*)(sm + SM_COL);           // [3][64], precomputed
    const unsigned sb = smem_u32(sm);

    const int tid  = threadIdx.x;
    const int lane = tid & 31;
    const int wid  = tid >> 5;
    const int span  = 2 * l + 1;
    const int ncols = 16 * span;

    // --- W: cp.async into the (soon-to-be per-warp EPI) staging region ---
    {
        const char* gw = (const char*)(wA + l * WBLK);
#pragma unroll
        for (int j = 0; j < 9; j++) {
            const int e = tid + 256 * j;
            if (e < 2176)
                CPA16(sb + SM_EPI + e * 16, gw + e * 16);
        }
        asm volatile("cp.async.commit_group;" ::: "memory");
    }

    // --- ALL coloff generations upfront (never rewritten) ---
    for (int e = tid; e < nt * 64; e += 256) {
        const int c  = t0 * 64 + e;
        const int cc = c < ncols ? c : ncols - 1;
        const int b  = cc / span;
        coloff[e] = b * XB_STRIDE + l * l + (cc - b * span);
    }
    asm volatile("cp.async.wait_group 0;" ::: "memory");
    __syncthreads();

    // --- HOIST: ldmatrix all 8 k-step A fragments once (W tile-invariant) ---
    const int m_base = wid * 16;
    unsigned aF[8][4];
    {
        const unsigned aoff = (unsigned)(m_base + (lane & 15)) * 272u
                            + (unsigned)(lane >> 4) * 16u;
        const unsigned aW = sb + SM_EPI + aoff;
#pragma unroll
        for (int ks = 0; ks < 8; ks++)
            LDSM4(aF[ks], aW + (unsigned)ks * 32u);
    }

    // --- X ownership: col xc, k in [kb,kb+32); eager fp16 pack (16 words) ---
    const int xc = tid & 63;
    const int kb = (tid >> 6) * 32;
    unsigned xh[16];
    {
        const float* xp = x + coloff[xc];
#pragma unroll
        for (int m = 0; m < 16; m++) {
            const __half h0 = __float2half_rn(xp[(kb + 2 * m) * P_TOT]);
            const __half h1 = __float2half_rn(xp[(kb + 2 * m + 1) * P_TOT]);
            xh[m] = ((unsigned)__half_as_ushort(h1) << 16) | __half_as_ushort(h0);
        }
    }

    // --- B fragment lane offset (applies to either buffer) ---
    const unsigned boff = (unsigned)(((lane & 7) | ((lane >> 4) << 3))) * 272u
                        + (unsigned)((lane >> 3) & 1) * 16u;

    // --- per-warp epilogue scratch: [16][72] floats at wid*4608 ---
    float* epw = (float*)(sm + SM_EPI + wid * 4608);

    for (int tt = 0; tt < nt; tt++) {
        const unsigned bbase = (tt & 1) ? SM_B1 : SM_B0;

        // --- STS xh(tt) -> B[tt&1] (safe: same-buffer reuse is 2 syncs apart)
        {
            char* dst = sm + bbase + xc * 272 + kb * 2;
            uint4 v0 = { xh[0],  xh[1],  xh[2],  xh[3]  };
            uint4 v1 = { xh[4],  xh[5],  xh[6],  xh[7]  };
            uint4 v2 = { xh[8],  xh[9],  xh[10], xh[11] };
            uint4 v3 = { xh[12], xh[13], xh[14], xh[15] };
            *(uint4*)(dst)      = v0;
            *(uint4*)(dst + 16) = v1;
            *(uint4*)(dst + 32) = v2;
            *(uint4*)(dst + 48) = v3;
        }
        __syncthreads();            // the ONLY CTA barrier per tile

        // --- LDG + convert X(tt+1) (lands during MMA below) ---
        if (tt + 1 < nt) {
            const float* xp = x + coloff[(tt + 1) * 64 + xc];
#pragma unroll
            for (int m = 0; m < 16; m++) {
                const __half h0 = __float2half_rn(xp[(kb + 2 * m) * P_TOT]);
                const __half h1 = __float2half_rn(xp[(kb + 2 * m + 1) * P_TOT]);
                xh[m] = ((unsigned)__half_as_ushort(h1) << 16) | __half_as_ushort(h0);
            }
        }

        // --- MMA: 8 k-steps, B-LDSM only, 8 independent acc chains ---
        const unsigned bB = sb + bbase + boff;
        float acc[8][4];
#pragma unroll
        for (int nq = 0; nq < 8; nq++)
#pragma unroll
            for (int j = 0; j < 4; j++) acc[nq][j] = 0.0f;

#pragma unroll
        for (int ks = 0; ks < 8; ks++) {
            const unsigned ko = (unsigned)ks * 32u;
            unsigned bf[4][4];
#pragma unroll
            for (int g = 0; g < 4; g++)
                LDSM4(bf[g], bB + (unsigned)g * (16u * 272u) + ko);
#pragma unroll
            for (int g = 0; g < 4; g++) {
                MMA16816(acc[2 * g],     aF[ks], bf[g][0], bf[g][1]);
                MMA16816(acc[2 * g + 1], aF[ks], bf[g][2], bf[g][3]);
            }
        }

        // --- WARP-LOCAL epilogue: transpose 16x64 block through private
        //     scratch, then coalesced guarded stores. No CTA sync. ---
        {
            const int r = lane >> 2;              // 0..7 (local row)
#pragma unroll
            for (int nq = 0; nq < 8; nq++) {
                const int cc = nq * 8 + (lane & 3) * 2;
                float2 lo = { acc[nq][0], acc[nq][1] };
                float2 hi = { acc[nq][2], acc[nq][3] };
                *(float2*)&epw[r * 72 + cc]       = lo;
                *(float2*)&epw[(r + 8) * 72 + cc] = hi;
            }
            __syncwarp();

            const int c0t = (t0 + tt) * 64;
#pragma unroll
            for (int h = 0; h < 2; h++) {
                const int c2 = lane + h * 32;
                if (c0t + c2 < ncols) {
                    float* op = out + coloff[tt * 64 + c2] + m_base * P_TOT;
                    const float* rp = epw + c2;
#pragma unroll
                    for (int rr = 0; rr < 16; rr++)
                        op[rr * P_TOT] = rp[rr * 72];
                }
            }
            __syncwarp();   // scratch reuse next tile is warp-internal
        }
    }
}

extern "C" void kernel_launch(void* const* d_in, const int* in_sizes, int n_in,
                              void* d_out, int out_size)
{
    const float* x = (const float*)d_in[0];      // [16,128,6561]
    const float* w = (const float*)d_in[1];      // [128,128,17,1]
    float* out = (float*)d_out;                  // [16,128,6561]

    cudaFuncSetAttribute(shconv_mma,
                         cudaFuncAttributeMaxDynamicSharedMemorySize, DSMEM);

    shconv_interp_pack<<<512, 256>>>(w);

    dim3 grid(14, NDEG);                         // 3-tile chunks x degrees
    shconv_mma<<<grid, 256, DSMEM>>>(x, out);
}